// round 1
// baseline (speedup 1.0000x reference)
#include <cuda_runtime.h>
#include <cstdint>

// BiLSTM_CRF: CRF forward (logZ) + Viterbi scan.
// feats [S,B,T] f32, mask [S,B] f32, transitions [T,T] f32.
// out (float32): [0,B) logZ, [B,2B) best_score, [2B, 2B+S*B*T) pointers.

constexpr int S = 1024, B = 1024, T = 32;
#define NEG_INF   (-10000.0f)
#define START_TAG 29
#define STOP_TAG  30

__device__ __forceinline__ unsigned long long fadd2(unsigned long long a, unsigned long long b) {
    unsigned long long r;
    asm("add.rn.f32x2 %0, %1, %2;" : "=l"(r) : "l"(a), "l"(b));
    return r;
}
__device__ __forceinline__ void ffma2(unsigned long long& d, unsigned long long a, unsigned long long b) {
    asm("fma.rn.f32x2 %0, %1, %2, %0;" : "+l"(d) : "l"(a), "l"(b));
}
__device__ __forceinline__ unsigned long long pack2(float lo, float hi) {
    unsigned long long r;
    asm("mov.b64 %0, {%1, %2};" : "=l"(r) : "f"(lo), "f"(hi));
    return r;
}
__device__ __forceinline__ void unpack2(unsigned long long v, float& lo, float& hi) {
    asm("mov.b64 {%0, %1}, %2;" : "=f"(lo), "=f"(hi) : "l"(v));
}

__global__ void __launch_bounds__(64) crf_kernel(
    const float* __restrict__ feats, const float* __restrict__ mask,
    const float* __restrict__ trans, float* __restrict__ out)
{
    // Per-warp double-buffered broadcast vector (warp0 = forward, warp1 = viterbi)
    __shared__ __align__(16) float buf[2][2][T];

    const int lane = threadIdx.x & 31;
    const int warp = threadIdx.x >> 5;
    const int b    = blockIdx.x;

    const float tstop = trans[STOP_TAG * T + lane];
    const float* mp = mask  + b;
    const float* fp = feats + b * T + lane;
    int pb = 0;

    if (warp == 0) {
        // ---------------- Forward: log partition ----------------
        // W_ij = exp(t_ij) precomputed (forbidden -1e4 entries underflow to exactly 0)
        unsigned long long W2[T / 2];
        #pragma unroll
        for (int k = 0; k < T / 2; k++)
            W2[k] = pack2(__expf(trans[lane * T + 2 * k]),
                          __expf(trans[lane * T + 2 * k + 1]));

        float alpha = (lane == START_TAG) ? 0.0f : NEG_INF;

        for (int s = 0; s < S; s++) {
            const float feat = __ldg(fp); fp += B * T;
            const float m    = __ldg(mp); mp += B;

            // M = max_j alpha_j (warp butterfly)
            float M = alpha;
            #pragma unroll
            for (int o = 16; o; o >>= 1)
                M = fmaxf(M, __shfl_xor_sync(0xffffffffu, M, o));

            buf[0][pb][lane] = __expf(alpha - M);   // E_j in [0,1]
            __syncwarp();

            const unsigned long long* e2 = (const unsigned long long*)buf[0][pb];
            unsigned long long acc0 = 0ull, acc1 = 0ull;  // {0.f,0.f}
            #pragma unroll
            for (int k = 0; k < T / 2; k += 2) {
                ffma2(acc0, e2[k],     W2[k]);
                ffma2(acc1, e2[k + 1], W2[k + 1]);
            }
            float a0, a1, b0, b1;
            unpack2(acc0, a0, a1); unpack2(acc1, b0, b1);
            const float sum = (a0 + a1) + (b0 + b1);

            // sum==0 only for the forbidden START row -> -inf; select (not multiply)
            // by mask keeps it NaN-free and it contributes exp(-inf)=0 downstream.
            const float anew = feat + M + __logf(sum);
            alpha = (m != 0.0f) ? anew : alpha;
            pb ^= 1;
        }

        // logZ = logsumexp(alpha + t[STOP,:])
        float v = alpha + tstop;
        float M = v;
        #pragma unroll
        for (int o = 16; o; o >>= 1)
            M = fmaxf(M, __shfl_xor_sync(0xffffffffu, M, o));
        float e = __expf(v - M);
        #pragma unroll
        for (int o = 16; o; o >>= 1)
            e += __shfl_xor_sync(0xffffffffu, e, o);
        if (lane == 0) out[b] = M + __logf(e);
    } else {
        // ---------------- Viterbi: max score + pointers ----------------
        unsigned long long T2[T / 2];
        #pragma unroll
        for (int k = 0; k < T / 2; k++)
            T2[k] = pack2(trans[lane * T + 2 * k], trans[lane * T + 2 * k + 1]);

        float sc = (lane == START_TAG) ? 0.0f : NEG_INF;
        float* pout = out + 2 * B + (size_t)b * T + lane;

        for (int s = 0; s < S; s++) {
            const float feat = __ldg(fp); fp += B * T;
            const float m    = __ldg(mp); mp += B;

            buf[1][pb][lane] = sc;
            __syncwarp();
            const unsigned long long* s2 = (const unsigned long long*)buf[1][pb];

            float best = -3.0e38f;
            float ptrf = 0.0f;
            #pragma unroll
            for (int k = 0; k < T / 2; k++) {
                float v0, v1;
                unpack2(fadd2(s2[k], T2[k]), v0, v1);
                // strict '>' with ascending j == first-index argmax (matches jnp.argmax)
                const bool c0 = v0 > best;
                best = c0 ? v0 : best;
                ptrf = c0 ? (float)(2 * k) : ptrf;
                const bool c1 = v1 > best;
                best = c1 ? v1 : best;
                ptrf = c1 ? (float)(2 * k + 1) : ptrf;
            }

            __stcs(pout, ptrf);            // streaming: don't pollute L2 (feats reuse)
            pout += B * T;

            const float snew = best + feat;
            sc = (m != 0.0f) ? snew : sc;  // bit-exact masked freeze
            pb ^= 1;
        }

        // best_score = max(scores + t[STOP,:])
        float v = sc + tstop;
        float M = v;
        #pragma unroll
        for (int o = 16; o; o >>= 1)
            M = fmaxf(M, __shfl_xor_sync(0xffffffffu, M, o));
        if (lane == 0) out[B + b] = M;
    }
}

extern "C" void kernel_launch(void* const* d_in, const int* in_sizes, int n_in,
                              void* d_out, int out_size) {
    const float* feats = (const float*)d_in[0];
    const float* mask  = (const float*)d_in[1];
    const float* trans = (const float*)d_in[2];
    crf_kernel<<<B, 64>>>(feats, mask, trans, (float*)d_out);
}

// round 4
// speedup vs baseline: 1.1746x; 1.1746x over previous
#include <cuda_runtime.h>
#include <cstdint>

// CRF forward (logZ) + Viterbi scan. Early-exit on monotone mask, 3-deep
// register prefetch of (feat, mask), exact argmax via FMNMX tree + eq-bitmap.
// feats [S,B,T] f32, mask [S,B] f32, transitions [T,T] f32.
// out (f32): [0,B) logZ, [B,2B) best_score, [2B, 2B+S*B*T) pointers.

constexpr int S = 1024, B = 1024, T = 32;
#define NEG_INF   (-10000.0f)
#define START_TAG 29
#define STOP_TAG  30

__device__ __forceinline__ unsigned long long fadd2(unsigned long long a, unsigned long long b) {
    unsigned long long r;
    asm("add.rn.f32x2 %0, %1, %2;" : "=l"(r) : "l"(a), "l"(b));
    return r;
}
__device__ __forceinline__ void ffma2(unsigned long long& d, unsigned long long a, unsigned long long b) {
    asm("fma.rn.f32x2 %0, %1, %2, %0;" : "+l"(d) : "l"(a), "l"(b));
}
__device__ __forceinline__ unsigned long long pack2(float lo, float hi) {
    unsigned long long r;
    asm("mov.b64 %0, {%1, %2};" : "=l"(r) : "f"(lo), "f"(hi));
    return r;
}
__device__ __forceinline__ void unpack2(unsigned long long v, float& lo, float& hi) {
    asm("mov.b64 {%0, %1}, %2;" : "=f"(lo), "=f"(hi) : "l"(v));
}

// Exact warp-max of a float via REDUX on an order-preserving int key.
__device__ __forceinline__ float warp_max_exact(float x) {
    int k = __float_as_int(x);
    k ^= (k >> 31) & 0x7fffffff;                 // monotone float->int map
    int km = __reduce_max_sync(0xffffffffu, k);
    km ^= (km >> 31) & 0x7fffffff;               // involution: map back
    return __int_as_float(km);
}

__global__ void __launch_bounds__(64) crf_kernel(
    const float* __restrict__ feats, const float* __restrict__ mask,
    const float* __restrict__ trans, float* __restrict__ out)
{
    __shared__ __align__(16) float buf[2][2][T];   // per-warp double-buffered broadcast

    const int lane = threadIdx.x & 31;
    const int warp = threadIdx.x >> 5;
    const int b    = blockIdx.x;

    const float tstop = trans[STOP_TAG * T + lane];
    const float* mp = mask  + b;
    const float* fp = feats + b * T + lane;
    int pb = 0;

    if (warp == 0) {
        // ---------------- Forward: log partition ----------------
        // W_ij = exp(t_ij); forbidden -1e4 entries underflow to exactly 0.
        unsigned long long W2[T / 2];
        #pragma unroll
        for (int k = 0; k < T / 2; k++)
            W2[k] = pack2(__expf(trans[lane * T + 2 * k]),
                          __expf(trans[lane * T + 2 * k + 1]));

        float alpha = (lane == START_TAG) ? 0.0f : NEG_INF;

        // 3-deep prefetch pipeline
        float f0 = __ldg(fp),             m0 = __ldg(mp);
        float f1 = __ldg(fp + B * T),     m1 = __ldg(mp + B);
        float f2 = __ldg(fp + 2 * B * T), m2 = __ldg(mp + 2 * B);
        fp += 3 * B * T; mp += 3 * B;

        for (int s = 0; s < S; s++) {
            if (m0 == 0.0f) break;                  // mask monotone: frozen forever
            const bool ld = (s + 3 < S);
            const float f3 = ld ? __ldg(fp) : 0.0f;
            const float m3 = ld ? __ldg(mp) : 0.0f;
            fp += B * T; mp += B;

            const float M = warp_max_exact(alpha);
            buf[0][pb][lane] = __expf(alpha - M);
            __syncwarp();

            const ulonglong2* e2 = (const ulonglong2*)buf[0][pb];
            unsigned long long acc0 = 0ull, acc1 = 0ull;
            #pragma unroll
            for (int k = 0; k < 8; k++) {           // 8 x 16B = all 32 floats
                const ulonglong2 q = e2[k];
                ffma2(acc0, q.x, W2[2 * k]);        // floats 4k..4k+1
                ffma2(acc1, q.y, W2[2 * k + 1]);    // floats 4k+2..4k+3
            }
            float a0, a1, b0, b1;
            unpack2(acc0, a0, a1); unpack2(acc1, b0, b1);
            const float sum = (a0 + a1) + (b0 + b1);

            alpha = f0 + M + __logf(sum);           // START row: log(0) = -inf, stays
            f0 = f1; m0 = m1; f1 = f2; m1 = m2; f2 = f3; m2 = m3;
            pb ^= 1;
        }

        // logZ = logsumexp(alpha + t[STOP,:])
        float v = alpha + tstop;
        float M = v;
        #pragma unroll
        for (int o = 16; o; o >>= 1)
            M = fmaxf(M, __shfl_xor_sync(0xffffffffu, M, o));
        float e = __expf(v - M);
        #pragma unroll
        for (int o = 16; o; o >>= 1)
            e += __shfl_xor_sync(0xffffffffu, e, o);
        if (lane == 0) out[b] = M + __logf(e);
    } else {
        // ---------------- Viterbi: max score + pointers ----------------
        unsigned long long T2[T / 2];
        #pragma unroll
        for (int k = 0; k < T / 2; k++)
            T2[k] = pack2(trans[lane * T + 2 * k], trans[lane * T + 2 * k + 1]);

        float sc = (lane == START_TAG) ? 0.0f : NEG_INF;
        float* pout = out + 2 * B + (long)b * T + lane;

        float f0 = __ldg(fp),             m0 = __ldg(mp);
        float f1 = __ldg(fp + B * T),     m1 = __ldg(mp + B);
        float f2 = __ldg(fp + 2 * B * T), m2 = __ldg(mp + 2 * B);
        fp += 3 * B * T; mp += 3 * B;

        int s = 0;
        float ptrf = 0.0f;
        bool frozen = false;
        for (; s < S; s++) {
            const bool ld = (s + 3 < S);
            const float f3 = ld ? __ldg(fp) : 0.0f;
            const float m3 = ld ? __ldg(mp) : 0.0f;
            fp += B * T; mp += B;

            buf[1][pb][lane] = sc;
            __syncwarp();
            const ulonglong2* s2 = (const ulonglong2*)buf[1][pb];

            // v_h = s_h + t[lane][h], h = 0..31 (all exact)
            float vv[T];
            #pragma unroll
            for (int k = 0; k < 8; k++) {
                const ulonglong2 q = s2[k];
                float x0, x1, y0, y1;
                unpack2(fadd2(q.x, T2[2 * k]),     x0, x1);
                unpack2(fadd2(q.y, T2[2 * k + 1]), y0, y1);
                vv[4 * k]     = x0; vv[4 * k + 1] = x1;
                vv[4 * k + 2] = y0; vv[4 * k + 3] = y1;
            }

            // Exact max via FMNMX tree (depth 5, 31 ops)
            float mx[T];
            #pragma unroll
            for (int h = 0; h < T; h++) mx[h] = vv[h];
            #pragma unroll
            for (int off = 16; off; off >>= 1)
                #pragma unroll
                for (int i = 0; i < 16; i++)
                    if (i < off) mx[i] = fmaxf(mx[i], mx[i + off]);
            const float vmax = mx[0];

            // First-index argmax: equality bitmap + ffs (independent FSETPs)
            unsigned eq = 0;
            #pragma unroll
            for (int h = 0; h < T; h++)
                if (vv[h] == vmax) eq |= (1u << h);
            const int k = __ffs(eq) - 1;

            ptrf = (float)k;
            __stcs(pout, ptrf);
            pout += B * T;

            if (m0 == 0.0f) { frozen = true; s++; break; }  // this step's ptr written

            sc = vmax + f0;                                  // exact update
            f0 = f1; m0 = m1; f1 = f2; m1 = m2; f2 = f3; m2 = m3;
            pb ^= 1;
        }

        if (frozen) {
            // Scores frozen => every remaining pointer equals ptrf.
            #pragma unroll 4
            for (; s < S; s++) { __stcs(pout, ptrf); pout += B * T; }
        }

        // best_score = max(sc + t[STOP,:])
        float v = sc + tstop;
        float M = v;
        #pragma unroll
        for (int o = 16; o; o >>= 1)
            M = fmaxf(M, __shfl_xor_sync(0xffffffffu, M, o));
        if (lane == 0) out[B + b] = M;
    }
}

extern "C" void kernel_launch(void* const* d_in, const int* in_sizes, int n_in,
                              void* d_out, int out_size) {
    const float* feats = (const float*)d_in[0];
    const float* mask  = (const float*)d_in[1];
    const float* trans = (const float*)d_in[2];
    crf_kernel<<<B, 64>>>(feats, mask, trans, (float*)d_out);
}

// round 5
// speedup vs baseline: 1.2645x; 1.0765x over previous
#include <cuda_runtime.h>
#include <cstdint>

// CRF forward (logZ) + Viterbi. Counted loops via binary-searched lengths
// (mask is monotone), rebased-normalizer forward (no warp reduction on the
// chain), 4-deep feat prefetch, exact fmax-tree + eq-bitmap argmax.
// feats [S,B,T] f32, mask [S,B] f32, transitions [T,T] f32.
// out (f32): [0,B) logZ, [B,2B) best_score, [2B, 2B+S*B*T) pointers.

constexpr int S = 1024, B = 1024, T = 32;
#define NEG_INF   (-10000.0f)
#define START_TAG 29
#define STOP_TAG  30

__device__ __forceinline__ unsigned long long fadd2(unsigned long long a, unsigned long long b) {
    unsigned long long r;
    asm("add.rn.f32x2 %0, %1, %2;" : "=l"(r) : "l"(a), "l"(b));
    return r;
}
__device__ __forceinline__ void ffma2(unsigned long long& d, unsigned long long a, unsigned long long b) {
    asm("fma.rn.f32x2 %0, %1, %2, %0;" : "+l"(d) : "l"(a), "l"(b));
}
__device__ __forceinline__ unsigned long long pack2(float lo, float hi) {
    unsigned long long r;
    asm("mov.b64 %0, {%1, %2};" : "=l"(r) : "f"(lo), "f"(hi));
    return r;
}
__device__ __forceinline__ void unpack2(unsigned long long v, float& lo, float& hi) {
    asm("mov.b64 {%0, %1}, %2;" : "=f"(lo), "=f"(hi) : "l"(v));
}

__global__ void __launch_bounds__(64) crf_kernel(
    const float* __restrict__ feats, const float* __restrict__ mask,
    const float* __restrict__ trans, float* __restrict__ out)
{
    __shared__ __align__(16) float buf[2][2][T];   // per-warp double-buffered broadcast

    const int lane = threadIdx.x & 31;
    const int warp = threadIdx.x >> 5;
    const int b    = blockIdx.x;

    // length = first s with mask[s][b]==0 (mask monotone). One-time search.
    int lo = 0, hi = S;
    #pragma unroll 1
    while (lo < hi) {
        const int mid = (lo + hi) >> 1;
        if (__ldg(mask + (size_t)mid * B + b) != 0.0f) lo = mid + 1; else hi = mid;
    }
    const int len = lo;

    const float tstop = __ldg(trans + STOP_TAG * T + lane);
    const float* fp = feats + b * T + lane;
    int pb = 0;

    if (warp == 0) {
        // ---------------- Forward: log partition ----------------
        // W_ij = exp(t_ij); forbidden -1e4 entries underflow to exactly 0.
        unsigned long long W2[T / 2];
        #pragma unroll
        for (int k = 0; k < T / 2; k++)
            W2[k] = pack2(__expf(__ldg(trans + lane * T + 2 * k)),
                          __expf(__ldg(trans + lane * T + 2 * k + 1)));

        // Rebased state: alpha = r + O. c = normalizer for this step's exp.
        float r = (lane == START_TAG) ? 0.0f : NEG_INF;
        float c = 0.0f;   // first-step normalizer = alpha0 max = 0
        float O = 0.0f;

        // 4-deep feat prefetch (loads beyond len but < S are harmless)
        float f0 = __ldg(fp);
        float f1 = (1 < S) ? __ldg(fp + 1 * B * T) : 0.0f;
        float f2 = (2 < S) ? __ldg(fp + 2 * B * T) : 0.0f;
        float f3 = (3 < S) ? __ldg(fp + 3 * B * T) : 0.0f;
        fp += 4 * (size_t)B * T;

        #pragma unroll 1
        for (int s = 0; s < len; s++) {
            const float f4 = (s + 4 < S) ? __ldg(fp) : 0.0f;
            fp += B * T;

            buf[0][pb][lane] = __expf(r - c);   // bounded args; -inf row -> 0
            __syncwarp();

            const ulonglong2* e2 = (const ulonglong2*)buf[0][pb];
            unsigned long long a0 = 0ull, a1 = 0ull, a2 = 0ull, a3 = 0ull;
            #pragma unroll
            for (int k = 0; k < 4; k++) {                 // 8 x 16B = all 32 floats
                const ulonglong2 qa = e2[2 * k];
                const ulonglong2 qb = e2[2 * k + 1];
                ffma2(a0, qa.x, W2[4 * k]);
                ffma2(a1, qa.y, W2[4 * k + 1]);
                ffma2(a2, qb.x, W2[4 * k + 2]);
                ffma2(a3, qb.y, W2[4 * k + 3]);
            }
            const unsigned long long sAB = fadd2(fadd2(a0, a1), fadd2(a2, a3));
            float sl, sh; unpack2(sAB, sl, sh);
            const float sum = sl + sh;

            r = f0 + __logf(sum);               // START row: log(0) = -inf, stays
            O += c;
            c = __shfl_sync(0xffffffffu, r, 0); // next step's normalizer, off-chain
            f0 = f1; f1 = f2; f2 = f3; f3 = f4;
            pb ^= 1;
        }

        // logZ = O + logsumexp(r + t[STOP,:])
        float v = r + tstop;
        float M = v;
        #pragma unroll
        for (int o = 16; o; o >>= 1)
            M = fmaxf(M, __shfl_xor_sync(0xffffffffu, M, o));
        float e = __expf(v - M);
        #pragma unroll
        for (int o = 16; o; o >>= 1)
            e += __shfl_xor_sync(0xffffffffu, e, o);
        if (lane == 0) out[b] = O + (M + __logf(e));
    } else {
        // ---------------- Viterbi: max score + pointers ----------------
        unsigned long long T2[T / 2];
        #pragma unroll
        for (int k = 0; k < T / 2; k++)
            T2[k] = pack2(__ldg(trans + lane * T + 2 * k),
                          __ldg(trans + lane * T + 2 * k + 1));

        float sc = (lane == START_TAG) ? 0.0f : NEG_INF;
        float* pout = out + 2 * B + (long)b * T + lane;

        float f0 = __ldg(fp);
        float f1 = (1 < S) ? __ldg(fp + 1 * B * T) : 0.0f;
        float f2 = (2 < S) ? __ldg(fp + 2 * B * T) : 0.0f;
        float f3 = (3 < S) ? __ldg(fp + 3 * B * T) : 0.0f;
        fp += 4 * (size_t)B * T;

        // One argmax step: vmax + first-index k from the state entering the step.
        // (macro-free lambda keeps it in registers)
        auto argmax_step = [&](int pbuf, float& vmax_out, int& k_out) {
            const ulonglong2* s2 = (const ulonglong2*)buf[1][pbuf];
            float vv[T];
            #pragma unroll
            for (int k = 0; k < 8; k++) {
                const ulonglong2 q = s2[k];
                float x0, x1, y0, y1;
                unpack2(fadd2(q.x, T2[2 * k]),     x0, x1);
                unpack2(fadd2(q.y, T2[2 * k + 1]), y0, y1);
                vv[4 * k]     = x0; vv[4 * k + 1] = x1;
                vv[4 * k + 2] = y0; vv[4 * k + 3] = y1;
            }
            float mx[T];
            #pragma unroll
            for (int h = 0; h < T; h++) mx[h] = vv[h];
            #pragma unroll
            for (int off = 16; off; off >>= 1)
                #pragma unroll
                for (int i = 0; i < 16; i++)
                    if (i < off) mx[i] = fmaxf(mx[i], mx[i + off]);
            const float vmax = mx[0];
            unsigned eq = 0;
            #pragma unroll
            for (int h = 0; h < T; h++)
                if (vv[h] == vmax) eq |= (1u << h);
            vmax_out = vmax;
            k_out = __ffs(eq) - 1;
        };

        #pragma unroll 1
        for (int s = 0; s < len; s++) {
            const float f4 = (s + 4 < S) ? __ldg(fp) : 0.0f;
            fp += B * T;

            buf[1][pb][lane] = sc;
            __syncwarp();

            float vmax; int k;
            argmax_step(pb, vmax, k);

            __stcs(pout, (float)k);
            pout += B * T;

            sc = vmax + f0;                     // exact update
            f0 = f1; f1 = f2; f2 = f3; f3 = f4;
            pb ^= 1;
        }

        if (len < S) {
            // Frozen scores: pointer is the same for all remaining steps.
            buf[1][pb][lane] = sc;
            __syncwarp();
            float vmax; int k;
            argmax_step(pb, vmax, k);
            const float ptrf = (float)k;
            #pragma unroll 4
            for (int s = len; s < S; s++) { __stcs(pout, ptrf); pout += B * T; }
        }

        // best_score = max(sc + t[STOP,:])
        float v = sc + tstop;
        float M = v;
        #pragma unroll
        for (int o = 16; o; o >>= 1)
            M = fmaxf(M, __shfl_xor_sync(0xffffffffu, M, o));
        if (lane == 0) out[B + b] = M;
    }
}

extern "C" void kernel_launch(void* const* d_in, const int* in_sizes, int n_in,
                              void* d_out, int out_size) {
    const float* feats = (const float*)d_in[0];
    const float* mask  = (const float*)d_in[1];
    const float* trans = (const float*)d_in[2];
    crf_kernel<<<B, 64>>>(feats, mask, trans, (float*)d_out);
}

// round 7
// speedup vs baseline: 1.6782x; 1.3271x over previous
#include <cuda_runtime.h>
#include <cstdint>

// CRF forward (logZ) + Viterbi merged into ONE warp per batch.
// Forward runs in the exp-domain with ratio renormalization (E_0 == 1 every
// step, zero-staleness): E' = (sum_i/sum_0) * exp(feat_i - feat_0).
// No log/ex2 on the critical chain. Counted loops via binary-searched length.
// out (f32): [0,B) logZ, [B,2B) best_score, [2B, 2B+S*B*T) pointers.

constexpr int S = 1024, B = 1024, T = 32;
#define NEG_INF   (-10000.0f)
#define START_TAG 29
#define STOP_TAG  30

__device__ __forceinline__ unsigned long long fadd2(unsigned long long a, unsigned long long b) {
    unsigned long long r;
    asm("add.rn.f32x2 %0, %1, %2;" : "=l"(r) : "l"(a), "l"(b));
    return r;
}
__device__ __forceinline__ void ffma2(unsigned long long& d, unsigned long long a, unsigned long long b) {
    asm("fma.rn.f32x2 %0, %1, %2, %0;" : "+l"(d) : "l"(a), "l"(b));
}
__device__ __forceinline__ unsigned long long pack2(float lo, float hi) {
    unsigned long long r;
    asm("mov.b64 %0, {%1, %2};" : "=l"(r) : "f"(lo), "f"(hi));
    return r;
}
__device__ __forceinline__ void unpack2(unsigned long long v, float& lo, float& hi) {
    asm("mov.b64 {%0, %1}, %2;" : "=f"(lo), "=f"(hi) : "l"(v));
}

__global__ void __launch_bounds__(32) crf_kernel(
    const float* __restrict__ feats, const float* __restrict__ mask,
    const float* __restrict__ trans, float* __restrict__ out)
{
    __shared__ __align__(16) float Eb[2][T];   // forward exp-state broadcast
    __shared__ __align__(16) float Sb[2][T];   // viterbi score broadcast

    const int lane = threadIdx.x;
    const int b    = blockIdx.x;

    // length = first s with mask[s][b]==0 (mask monotone). One-time search.
    int lo = 0, hi = S;
    #pragma unroll 1
    while (lo < hi) {
        const int mid = (lo + hi) >> 1;
        if (__ldg(mask + (size_t)mid * B + b) != 0.0f) lo = mid + 1; else hi = mid;
    }
    const int len = lo;

    const float L2E = 1.4426950408889634f;

    // Per-lane transition row (lane = target tag i). W = exp(t) for forward
    // (forbidden -1e4 entries underflow to exactly 0 == contributing -inf).
    unsigned long long W2[T / 2], T2[T / 2];
    #pragma unroll
    for (int k = 0; k < T / 2; k++) {
        const float t0 = __ldg(trans + lane * T + 2 * k);
        const float t1 = __ldg(trans + lane * T + 2 * k + 1);
        T2[k] = pack2(t0, t1);
        W2[k] = pack2(__expf(t0), __expf(t1));
    }
    const float tstop = __ldg(trans + STOP_TAG * T + lane);

    // State: alpha = log(E) + O; E_START-row stays 0 (forbidden).
    float Ev = (lane == START_TAG) ? 1.0f : 0.0f;   // exp(alpha0 - 0)
    float sc = (lane == START_TAG) ? 0.0f : NEG_INF;
    float O  = 0.0f;

    Eb[0][lane] = Ev;
    Sb[0][lane] = sc;
    __syncwarp();

    const size_t BT = (size_t)B * T;
    const float* fp = feats + (size_t)b * T + lane;
    float fq[4];
    #pragma unroll
    for (int k = 0; k < 4; k++) fq[k] = __ldg(fp + (size_t)k * BT);
    float* pout = out + 2 * B + (size_t)b * T + lane;

    #pragma unroll 4
    for (int s = 0; s < len; s++) {
        const int j  = s & 3;
        const int pb = s & 1;
        const float fv = fq[j];
        const int pfr = (s + 4 < S) ? (s + 4) : (S - 1);
        fq[j] = __ldg(fp + (size_t)pfr * BT);      // forced MLP=4 prefetch

        // Off-chain: X_i = exp(feat_i - feat_0), bounded args.
        const float fv0 = __shfl_sync(0xffffffffu, fv, 0);
        float X;
        asm("ex2.approx.ftz.f32 %0, %1;" : "=f"(X) : "f"((fv - fv0) * L2E));

        // ---------- Viterbi chain ----------
        const ulonglong2* s2 = (const ulonglong2*)Sb[pb];
        float vv[T];
        #pragma unroll
        for (int k = 0; k < 8; k++) {
            const ulonglong2 q = s2[k];
            float x0, x1, y0, y1;
            unpack2(fadd2(q.x, T2[2 * k]),     x0, x1);
            unpack2(fadd2(q.y, T2[2 * k + 1]), y0, y1);
            vv[4 * k]     = x0; vv[4 * k + 1] = x1;
            vv[4 * k + 2] = y0; vv[4 * k + 3] = y1;
        }
        float mx[16];
        #pragma unroll
        for (int i = 0; i < 16; i++) mx[i] = fmaxf(vv[i], vv[i + 16]);
        #pragma unroll
        for (int off = 8; off; off >>= 1)
            #pragma unroll
            for (int i = 0; i < 8; i++)
                if (i < off) mx[i] = fmaxf(mx[i], mx[i + off]);
        const float vmax = mx[0];
        sc = vmax + fv;                             // exact update

        // ---------- Forward chain (no log/exp) ----------
        const ulonglong2* e2 = (const ulonglong2*)Eb[pb];
        unsigned long long a0 = 0ull, a1 = 0ull, a2 = 0ull, a3 = 0ull;
        #pragma unroll
        for (int k = 0; k < 4; k++) {
            const ulonglong2 qa = e2[2 * k];
            const ulonglong2 qb = e2[2 * k + 1];
            ffma2(a0, qa.x, W2[4 * k]);
            ffma2(a1, qa.y, W2[4 * k + 1]);
            ffma2(a2, qb.x, W2[4 * k + 2]);
            ffma2(a3, qb.y, W2[4 * k + 3]);
        }
        const unsigned long long sAB = fadd2(fadd2(a0, a1), fadd2(a2, a3));
        float sl, sh; unpack2(sAB, sl, sh);
        const float sum = sl + sh;                  // sum_i; lane29 row -> 0

        const float s0 = __shfl_sync(0xffffffffu, sum, 0);
        float rs0;
        asm("rcp.approx.ftz.f32 %0, %1;" : "=f"(rs0) : "f"(s0));
        Ev = (sum * rs0) * X;                       // E' ; E'_0 == 1 (stable)

        Eb[pb ^ 1][lane] = Ev;
        Sb[pb ^ 1][lane] = sc;
        __syncwarp();

        // ---------- off-chain: offset accumulation + exact argmax + store ----------
        O += fv0 + __logf(s0);                      // c_{s+1}; result used only at end
        unsigned eq = 0;
        #pragma unroll
        for (int h = 0; h < T; h++)
            if (vv[h] == vmax) eq |= (1u << h);
        __stcs(pout, (float)(__ffs(eq) - 1));
        pout += BT;
    }

    if (len < S) {
        // Frozen scores: Sb[len&1] already holds final sc (written+synced in
        // the last iteration). One more argmax gives the tail pointer.
        const ulonglong2* s2 = (const ulonglong2*)Sb[len & 1];
        float vv[T];
        #pragma unroll
        for (int k = 0; k < 8; k++) {
            const ulonglong2 q = s2[k];
            float x0, x1, y0, y1;
            unpack2(fadd2(q.x, T2[2 * k]),     x0, x1);
            unpack2(fadd2(q.y, T2[2 * k + 1]), y0, y1);
            vv[4 * k]     = x0; vv[4 * k + 1] = x1;
            vv[4 * k + 2] = y0; vv[4 * k + 3] = y1;
        }
        float mx[16];
        #pragma unroll
        for (int i = 0; i < 16; i++) mx[i] = fmaxf(vv[i], vv[i + 16]);
        #pragma unroll
        for (int off = 8; off; off >>= 1)
            #pragma unroll
            for (int i = 0; i < 8; i++)
                if (i < off) mx[i] = fmaxf(mx[i], mx[i + off]);
        const float vmax = mx[0];
        unsigned eq = 0;
        #pragma unroll
        for (int h = 0; h < T; h++)
            if (vv[h] == vmax) eq |= (1u << h);
        const float pv = (float)(__ffs(eq) - 1);
        #pragma unroll 4
        for (int s = len; s < S; s++) { __stcs(pout, pv); pout += BT; }
    }

    // logZ = O + log( sum_i E_i * exp(tstop_i) )   (E bounded, no max needed)
    {
        float z = Ev * __expf(tstop);
        #pragma unroll
        for (int o = 16; o; o >>= 1)
            z += __shfl_xor_sync(0xffffffffu, z, o);
        if (lane == 0) out[b] = O + __logf(z);
    }
    // best_score = max(sc + t[STOP,:])
    {
        float v = sc + tstop;
        #pragma unroll
        for (int o = 16; o; o >>= 1)
            v = fmaxf(v, __shfl_xor_sync(0xffffffffu, v, o));
        if (lane == 0) out[B + b] = v;
    }
}

extern "C" void kernel_launch(void* const* d_in, const int* in_sizes, int n_in,
                              void* d_out, int out_size) {
    const float* feats = (const float*)d_in[0];
    const float* mask  = (const float*)d_in[1];
    const float* trans = (const float*)d_in[2];
    crf_kernel<<<B, 32>>>(feats, mask, trans, (float*)d_out);
}